// round 11
// baseline (speedup 1.0000x reference)
#include <cuda_runtime.h>
#include <cstdint>

// FlowEmbedder cost, round 11: FULL-SCALAR variant of the R10 algorithm.
// Tests the hypothesis that packed f32x2 RAW latency (unprobed, PTX-only
// path) is what pinned R3-R10 at ~10.4us despite nothing saturating.
// All chain/coefficient math is scalar lat-4 FMUL/FFMA with immediate
// multipliers where possible (FFMA-imm rt=1), masks via FSETP-imm + FSEL,
// accumulate via FFMA(e,1.0,acc) imm-form.
//
// cost_i = 0.02*n_i + sum_{s=0}^{14} m_s * (0.08 * 2^{g_i(s)})
//   g(s) = k0 + k1 s + k2 s^2 + k3 s^3   (k's include -log2(e))
//   chains: A covers s=0..7 (seeds at 0), B covers s=8..14 (seeds at 8)
//   m_s = (nf > s) float compare, nf = floor(euc/0.1)+1 exact small int.

__device__ __forceinline__ float ex2_ap(float x) {
    float r; asm("ex2.approx.f32 %0, %1;" : "=f"(r) : "f"(x)); return r;
}
__device__ __forceinline__ float rsq_ap(float x) {
    float r; asm("rsqrt.approx.f32 %0, %1;" : "=f"(r) : "f"(x)); return r;
}
// em = (nf > sf) ? e : 0   — FSETP(imm) + FSEL, no int conversions
__device__ __forceinline__ float fmask(float nf, float sf, float e) {
    float m;
    asm("{ .reg .pred p; setp.gt.f32 p, %1, %2;\n\t"
        "  selp.f32 %0, %3, 0f00000000, p; }"
        : "=f"(m) : "f"(nf), "f"(sf), "f"(e));
    return m;
}

__device__ __forceinline__ float pair_cost(float ax, float ay, float bx, float by,
                                           float p00, float p01, float p10,
                                           float p11, float p20, float p21) {
    // ---- prologue ------------------------------------------------------
    float dx = bx - ax, dy = by - ay;
    float d2 = fmaf(dx, dx, dy * dy);
    float euc = __fsqrt_rn(d2);                       // IEEE, matches ref

    // correctly-rounded euc/0.1 (== __fdiv_rn; fl(1/0.1f)==10.0f exactly)
    float t = euc * 10.0f;
    float q = fmaf(fmaf(-0.1f, t, euc), 10.0f, t);
    float nf = floorf(q) + 1.0f;                      // exact small int

    float inv = rsq_ap(d2);                           // 1/euc (loose path)
    float h = (0.1f * dx) * inv;
    float g = (0.1f * dy) * inv;

    // ---- cubic coefficients k0..k3 (scaled by -log2 e via params) ------
    float c0 = fmaf(p00, dx, p01 * dy);
    float c1 = fmaf(p10, dx, p11 * dy);
    float c2 = fmaf(p20, dx, p21 * dy);

    float xx = ax * ax, xy = ax * ay, yy = ay * ay;
    float hh = h * h,  hg = h * g,  gg = g * g;
    float c2yy = c2 * yy;
    float c2gg = c2 * gg;

    float k0 = ax * fmaf(c0, xx, fmaf(c1, xy, c2yy));
    float k3 = h  * fmaf(c0, hh, fmaf(c1, hg, c2gg));

    // k1 = c0*3XX*H + c1*(2XY*H + XX*G) + c2*(YY*H + 2XY*G)
    float xx3 = 3.0f * xx;
    float xy2 = 2.0f * xy;
    float t0 = xx3 * h;
    float t1 = fmaf(xy2, h, xx * g);
    float t2 = fmaf(xy2, g, yy * h);
    float k1 = fmaf(c0, t0, fmaf(c1, t1, c2 * t2));
    // k2 = c0*3HH*X + c1*(2HG*X + HH*Y) + c2*(GG*X + 2HG*Y)
    float hh3 = 3.0f * hh;
    float hg2 = 2.0f * hg;
    float u0 = hh3 * ax;
    float u1 = fmaf(hg2, ax, hh * ay);
    float u2 = fmaf(hg2, ay, gg * ax);
    float k2 = fmaf(c0, u0, fmaf(c1, u1, c2 * u2));

    // ---- seeds ---------------------------------------------------------
    const float L2008 = -3.6438561897747253f;         // log2(0.08)
    float k22  = k2 + k2;
    float dg0  = k1 + (k2 + k3);                      // dg(0)=k1+k2+k3
    float d2g0 = fmaf(k3, 6.0f, k22);                 // 2k2+6k3
    float w6   = 6.0f * k3;                           // 6k3
    float g8   = fmaf(fmaf(fmaf(k3, 8.0f, k2), 8.0f, k1), 8.0f, k0);
    float dg8  = fmaf(k2, 17.0f, fmaf(k3, 217.0f, k1));
    float d2g8 = fmaf(k3, 54.0f, k22);

    float EA = ex2_ap(k0 + L2008);                    // 0.08*2^{g(0)}
    float RA = ex2_ap(dg0);
    float QA = ex2_ap(d2g0);
    float W  = ex2_ap(w6);
    float EB = ex2_ap(g8 + L2008);                    // 0.08*2^{g(8)}
    float RB = ex2_ap(dg8);
    float QB = ex2_ap(d2g8);

    // ---- chain A: s = 0..7 (s=0 always valid since n >= 1) -------------
    float accA = EA;
    float accA2 = 0.0f;
#pragma unroll
    for (int s = 1; s < 8; ++s) {
        EA = EA * RA;                                 // e(s)
        if (s < 7) RA = RA * QA;
        if (s < 6) QA = QA * W;
        float em = fmask(nf, (float)s, EA);
        if (s & 1) accA  = fmaf(em, 1.0f, accA);      // FFMA-imm rt=1
        else       accA2 = fmaf(em, 1.0f, accA2);
    }
    // ---- chain B: s = 8..14 --------------------------------------------
    float accB = fmask(nf, 8.0f, EB);
    float accB2 = 0.0f;
#pragma unroll
    for (int s = 9; s < 15; ++s) {
        EB = EB * RB;
        if (s < 14) RB = RB * QB;
        if (s < 13) QB = QB * W;
        float em = fmask(nf, (float)s, EB);
        if (s & 1) accB  = fmaf(em, 1.0f, accB);
        else       accB2 = fmaf(em, 1.0f, accB2);
    }

    float acc = (accA + accA2) + (accB + accB2);
    return fmaf(0.02f, nf, acc);
}

__global__ void __launch_bounds__(256)
flow_cost_kernel(const float4* __restrict__ x1,
                 const float4* __restrict__ x2,
                 const float* __restrict__ pp,
                 float* __restrict__ out,
                 int n_pairs) {
    int i = blockIdx.x * blockDim.x + threadIdx.x;  // 2 pairs per thread
    int base = 2 * i;
    if (base >= n_pairs) return;

    const float NL2E = -1.4426950408889634f;
    float p00 = NL2E * pp[0], p01 = NL2E * pp[1];
    float p10 = (3.0f * NL2E) * pp[2], p11 = (3.0f * NL2E) * pp[3];
    float p20 = (3.0f * NL2E) * pp[4], p21 = (3.0f * NL2E) * pp[5];

    if (base + 1 < n_pairs) {
        float4 a = x1[i];
        float4 b = x2[i];
        float c0 = pair_cost(a.x, a.y, b.x, b.y, p00, p01, p10, p11, p20, p21);
        float c1 = pair_cost(a.z, a.w, b.z, b.w, p00, p01, p10, p11, p20, p21);
        *reinterpret_cast<float2*>(out + base) = make_float2(c0, c1);
    } else {
        const float2* x1s = reinterpret_cast<const float2*>(x1);
        const float2* x2s = reinterpret_cast<const float2*>(x2);
        float2 a = x1s[base];
        float2 b = x2s[base];
        out[base] = pair_cost(a.x, a.y, b.x, b.y, p00, p01, p10, p11, p20, p21);
    }
}

extern "C" void kernel_launch(void* const* d_in, const int* in_sizes, int n_in,
                              void* d_out, int out_size) {
    const float4* x1 = (const float4*)d_in[0];
    const float4* x2 = (const float4*)d_in[1];
    const float*  pp = (const float*)d_in[2];
    float* out = (float*)d_out;

    int n_pairs = out_size;
    int n_threads_total = (n_pairs + 1) / 2;
    int threads = 256;
    int blocks = (n_threads_total + threads - 1) / threads;
    flow_cost_kernel<<<blocks, threads>>>(x1, x2, pp, out, n_pairs);
}

// round 12
// speedup vs baseline: 1.1603x; 1.1603x over previous
#include <cuda_runtime.h>
#include <cstdint>

// FlowEmbedder cost, round 12: R6 body (measured best, 10.34us kernel) plus
// exact work removal:
//  - s=0 accumulate folded (mask is always 1 since n>=1)
//  - warp-uniform vote (REDUX.MAX on float bits) skips steps 12/13/14 and
//    their feeding chain updates when no pair in the warp needs them
//    (P(skip) ~ 0.38/0.30/0.28 per tier).
//
// cost_i = 0.02*n_i + sum_{s=0}^{14} m_s * (0.08 * 2^{g_i(s)})
//   g(s) = k0 + k1 s + k2 s^2 + k3 s^3   (k's include -log2(e))
//   m_s  = saturate(nf - s)  in {0.0, 1.0} exactly, nf = floor(euc/0.1)+1
// Split forward-difference product chains (s=0..7 / s=8..14), f32x2 packed
// over 2 pairs/thread, 0.08 folded into the ex2 seeds.

typedef unsigned long long u64;

__device__ __forceinline__ u64 pk2(float lo, float hi) {
    u64 r; asm("mov.b64 %0, {%1, %2};" : "=l"(r) : "f"(lo), "f"(hi)); return r;
}
__device__ __forceinline__ void upk2(float& lo, float& hi, u64 v) {
    asm("mov.b64 {%0, %1}, %2;" : "=f"(lo), "=f"(hi) : "l"(v));
}
__device__ __forceinline__ u64 mul2(u64 a, u64 b) {
    u64 d; asm("mul.rn.f32x2 %0, %1, %2;" : "=l"(d) : "l"(a), "l"(b)); return d;
}
__device__ __forceinline__ u64 add2(u64 a, u64 b) {
    u64 d; asm("add.rn.f32x2 %0, %1, %2;" : "=l"(d) : "l"(a), "l"(b)); return d;
}
__device__ __forceinline__ u64 fma2(u64 a, u64 b, u64 c) {
    u64 d; asm("fma.rn.f32x2 %0, %1, %2, %3;" : "=l"(d) : "l"(a), "l"(b), "l"(c)); return d;
}
__device__ __forceinline__ u64 ex2_2(u64 g) {
    float a, b; upk2(a, b, g);
    asm("ex2.approx.f32 %0, %1;" : "=f"(a) : "f"(a));
    asm("ex2.approx.f32 %0, %1;" : "=f"(b) : "f"(b));
    return pk2(a, b);
}
__device__ __forceinline__ float rsq_ap(float x) {
    float r; asm("rsqrt.approx.f32 %0, %1;" : "=f"(r) : "f"(x)); return r;
}

__global__ void __launch_bounds__(256)
flow_cost_kernel(const float4* __restrict__ x1,
                 const float4* __restrict__ x2,
                 const float* __restrict__ pp,
                 float* __restrict__ out,
                 int n_pairs) {
    int i = blockIdx.x * blockDim.x + threadIdx.x;  // 2 pairs per thread
    int base = 2 * i;
    if (base >= n_pairs) return;

    const float NL2E = -1.4426950408889634f;
    float p00 = NL2E * pp[0], p01 = NL2E * pp[1];
    float p10 = (3.0f * NL2E) * pp[2], p11 = (3.0f * NL2E) * pp[3];
    float p20 = (3.0f * NL2E) * pp[4], p21 = (3.0f * NL2E) * pp[5];
    u64 P00 = pk2(p00, p00), P01 = pk2(p01, p01);
    u64 P10 = pk2(p10, p10), P11 = pk2(p11, p11);
    u64 P20 = pk2(p20, p20), P21 = pk2(p21, p21);

    float ax0, ay0, bx0, by0, ax1, ay1, bx1, by1;
    bool full = (base + 1 < n_pairs);
    if (full) {
        float4 a = x1[i];
        float4 b = x2[i];
        ax0 = a.x; ay0 = a.y; ax1 = a.z; ay1 = a.w;
        bx0 = b.x; by0 = b.y; bx1 = b.z; by1 = b.w;
    } else {
        const float2* x1s = reinterpret_cast<const float2*>(x1);
        const float2* x2s = reinterpret_cast<const float2*>(x2);
        float2 a = x1s[base];
        float2 b = x2s[base];
        ax0 = ax1 = a.x; ay0 = ay1 = a.y;
        bx0 = bx1 = b.x; by0 = by1 = b.y;
    }

    // ---- scalar per-pair prologue -------------------------------------
    float dx0 = bx0 - ax0, dy0 = by0 - ay0;
    float dx1 = bx1 - ax1, dy1 = by1 - ay1;
    float d2_0 = fmaf(dx0, dx0, dy0 * dy0);
    float d2_1 = fmaf(dx1, dx1, dy1 * dy1);
    float euc0 = __fsqrt_rn(d2_0);
    float euc1 = __fsqrt_rn(d2_1);

    // correctly-rounded euc/0.1 (== __fdiv_rn, fl(1/0.1f)==10.0f exactly)
    float t0 = euc0 * 10.0f;
    float nf0 = floorf(fmaf(fmaf(-0.1f, t0, euc0), 10.0f, t0)) + 1.0f;
    float t1 = euc1 * 10.0f;
    float nf1 = floorf(fmaf(fmaf(-0.1f, t1, euc1), 10.0f, t1)) + 1.0f;

    // warp-uniform max n (positive floats order as uint bit patterns)
    unsigned mk = __activemask();
    unsigned nmax_bits = __reduce_max_sync(mk, __float_as_uint(fmaxf(nf0, nf1)));
    float nmaxf = __uint_as_float(nmax_bits);

    float rs0 = rsq_ap(d2_0), rs1 = rsq_ap(d2_1);
    float h0 = (0.1f * dx0) * rs0, g0 = (0.1f * dy0) * rs0;
    float h1 = (0.1f * dx1) * rs1, g1 = (0.1f * dy1) * rs1;

    // ---- packed coefficient pipeline ----------------------------------
    u64 DX = pk2(dx0, dx1), DY = pk2(dy0, dy1);
    u64 X = pk2(ax0, ax1), Y = pk2(ay0, ay1);
    u64 H = pk2(h0, h1), G = pk2(g0, g1);

    u64 C0 = fma2(P01, DY, mul2(P00, DX));
    u64 C1 = fma2(P11, DY, mul2(P10, DX));
    u64 C2 = fma2(P21, DY, mul2(P20, DX));

    u64 XX = mul2(X, X), XY = mul2(X, Y), YY = mul2(Y, Y);
    u64 HH = mul2(H, H), HG = mul2(H, G), GG = mul2(G, G);
    u64 c2yy = mul2(C2, YY);
    u64 c2gg = mul2(C2, GG);

    u64 K0 = mul2(X, fma2(C0, XX, fma2(C1, XY, c2yy)));
    u64 K3 = mul2(H, fma2(C0, HH, fma2(C1, HG, c2gg)));

    u64 C0_3 = add2(C0, add2(C0, C0));
    u64 C1_2 = add2(C1, C1);
    u64 C2_2 = add2(C2, C2);

    u64 gx0 = fma2(C0_3, XX, fma2(C1_2, XY, c2yy));
    u64 gy0 = fma2(C1, XX, mul2(C2_2, XY));
    u64 K1 = fma2(G, gy0, mul2(H, gx0));
    u64 gx1 = fma2(C0_3, HH, fma2(C1_2, HG, c2gg));
    u64 gy1 = fma2(C1, HH, mul2(C2_2, HG));
    u64 K2 = fma2(Y, gy1, mul2(X, gx1));

    // ---- seeds (0.08 folded into E seeds) ------------------------------
    const u64 THREE2 = 0x4040000040400000ULL;  // {3,3}
    const u64 SIX2   = 0x40C0000040C00000ULL;  // {6,6}
    const u64 EIGHT2 = 0x4100000041000000ULL;  // {8,8}
    const u64 C17    = 0x4188000041880000ULL;  // {17,17}
    const u64 C217   = 0x4359000043590000ULL;  // {217,217}
    const u64 C54    = 0x4258000042580000ULL;  // {54,54}
    const u64 L2008  = 0xC0693574C0693574ULL;  // {log2(0.08), log2(0.08)}

    u64 DG  = add2(K1, add2(K2, K3));               // dg(0)
    u64 tt  = fma2(K3, THREE2, K2);
    u64 D2G = add2(tt, tt);                         // d2g(0)
    u64 W6  = mul2(K3, SIX2);                       // 6k3

    u64 G8   = fma2(fma2(fma2(K3, EIGHT2, K2), EIGHT2, K1), EIGHT2, K0);
    u64 DG8  = fma2(K2, C17, fma2(K3, C217, K1));   // dg(8)
    u64 D2G8 = fma2(K3, C54, add2(K2, K2));         // d2g(8)

    u64 EA = ex2_2(add2(K0, L2008));   // 0.08 * 2^{g(0)}
    u64 RA = ex2_2(DG);
    u64 QA = ex2_2(D2G);
    u64 W  = ex2_2(W6);
    u64 EB = ex2_2(add2(G8, L2008));   // 0.08 * 2^{g(8)}
    u64 RB = ex2_2(DG8);
    u64 QB = ex2_2(D2G8);

    // ---- chain A: s=0 folded (mask always 1), s=1..7 masked ------------
    u64 accA = EA;
#pragma unroll
    for (int s = 1; s < 8; ++s) {
        EA = mul2(EA, RA);                       // e(s)
        if (s < 7) RA = mul2(RA, QA);
        if (s < 6) QA = mul2(QA, W);
        float m0 = __saturatef(nf0 - (float)s);  // exactly 1.0 or 0.0
        float m1 = __saturatef(nf1 - (float)s);
        accA = fma2(EA, pk2(m0, m1), accA);
    }

    // ---- chain B: s=8..11 always; 12/13/14 gated by warp-uniform vote --
    u64 accB = 0;
#pragma unroll
    for (int s = 8; s < 12; ++s) {
        float m0 = __saturatef(nf0 - (float)s);
        float m1 = __saturatef(nf1 - (float)s);
        accB = fma2(EB, pk2(m0, m1), accB);
        EB = mul2(EB, RB);
        if (s < 11) RB = mul2(RB, QB);
        if (s < 11) QB = mul2(QB, W);
    }
    if (nmaxf > 12.0f) {                 // some pair needs step 12
        float m0 = __saturatef(nf0 - 12.0f);
        float m1 = __saturatef(nf1 - 12.0f);
        accB = fma2(EB, pk2(m0, m1), accB);
        if (nmaxf > 13.0f) {             // some pair needs step 13
            RB = mul2(RB, QB);           // R12 (uses Q11)
            EB = mul2(EB, RB);           // e(13)
            m0 = __saturatef(nf0 - 13.0f);
            m1 = __saturatef(nf1 - 13.0f);
            accB = fma2(EB, pk2(m0, m1), accB);
            if (nmaxf > 14.0f) {         // some pair needs step 14
                QB = mul2(QB, W);        // Q12
                RB = mul2(RB, QB);       // R13
                EB = mul2(EB, RB);       // e(14)
                m0 = __saturatef(nf0 - 14.0f);
                m1 = __saturatef(nf1 - 14.0f);
                accB = fma2(EB, pk2(m0, m1), accB);
            }
        }
    }

    u64 ACC = add2(accA, accB);
    float a0, a1;
    upk2(a0, a1, ACC);
    float c0 = fmaf(0.02f, nf0, a0);
    float c1 = fmaf(0.02f, nf1, a1);

    if (full) {
        *reinterpret_cast<float2*>(out + base) = make_float2(c0, c1);
    } else {
        out[base] = c0;
    }
}

extern "C" void kernel_launch(void* const* d_in, const int* in_sizes, int n_in,
                              void* d_out, int out_size) {
    const float4* x1 = (const float4*)d_in[0];
    const float4* x2 = (const float4*)d_in[1];
    const float*  pp = (const float*)d_in[2];
    float* out = (float*)d_out;

    int n_pairs = out_size;
    int n_threads_total = (n_pairs + 1) / 2;
    int threads = 256;
    int blocks = (n_threads_total + threads - 1) / threads;
    flow_cost_kernel<<<blocks, threads>>>(x1, x2, pp, out, n_pairs);
}

// round 13
// speedup vs baseline: 1.1881x; 1.0239x over previous
#include <cuda_runtime.h>
#include <cstdint>

// FlowEmbedder cost, round 13: SINGLE 15-step chain (R3 structure) with all
// R12-validated trims. Rationale: R3 (single, depth 14) == R6 (split) at
// 10.34us -> chain depth is free; the split only added 3 extra ex2 seeds and
// their derivation (~19 instr). Prologue+seeds dominated R12's budget, so
// cut them. Keeps: sat-masks (exact {0,1}), s=0 accumulate fold, 0.08 folded
// into the ex2 seed, warp-uniform REDUX vote gating steps 12/13/14 with the
// feeding chain muls (q10/r11/e12 etc.) deferred into the gates.
//
// cost_i = 0.02*n_i + sum_{s=0}^{n_i-1} 0.08 * 2^{g_i(s)}
//   g(s) = k0 + k1 s + k2 s^2 + k3 s^3   (k's include -log2(e))
//   e(s+1)=e(s)*r(s); r(s+1)=r(s)*q(s); q(s+1)=q(s)*w
//   seeds: e0=0.08*2^{k0}, r0=2^{k1+k2+k3}, q0=2^{2k2+6k3}, w=2^{6k3}
// n_i = floor(euc/0.1)+1 via bit-exact IEEE sqrt + correctly-rounded
// Markstein division (fl(1/0.1f)==10.0f exactly). 2 pairs/thread, f32x2.

typedef unsigned long long u64;

__device__ __forceinline__ u64 pk2(float lo, float hi) {
    u64 r; asm("mov.b64 %0, {%1, %2};" : "=l"(r) : "f"(lo), "f"(hi)); return r;
}
__device__ __forceinline__ void upk2(float& lo, float& hi, u64 v) {
    asm("mov.b64 {%0, %1}, %2;" : "=f"(lo), "=f"(hi) : "l"(v));
}
__device__ __forceinline__ u64 mul2(u64 a, u64 b) {
    u64 d; asm("mul.rn.f32x2 %0, %1, %2;" : "=l"(d) : "l"(a), "l"(b)); return d;
}
__device__ __forceinline__ u64 add2(u64 a, u64 b) {
    u64 d; asm("add.rn.f32x2 %0, %1, %2;" : "=l"(d) : "l"(a), "l"(b)); return d;
}
__device__ __forceinline__ u64 fma2(u64 a, u64 b, u64 c) {
    u64 d; asm("fma.rn.f32x2 %0, %1, %2, %3;" : "=l"(d) : "l"(a), "l"(b), "l"(c)); return d;
}
__device__ __forceinline__ u64 ex2_2(u64 g) {
    float a, b; upk2(a, b, g);
    asm("ex2.approx.f32 %0, %1;" : "=f"(a) : "f"(a));
    asm("ex2.approx.f32 %0, %1;" : "=f"(b) : "f"(b));
    return pk2(a, b);
}
__device__ __forceinline__ float rsq_ap(float x) {
    float r; asm("rsqrt.approx.f32 %0, %1;" : "=f"(r) : "f"(x)); return r;
}

__global__ void __launch_bounds__(256)
flow_cost_kernel(const float4* __restrict__ x1,
                 const float4* __restrict__ x2,
                 const float* __restrict__ pp,
                 float* __restrict__ out,
                 int n_pairs) {
    int i = blockIdx.x * blockDim.x + threadIdx.x;  // 2 pairs per thread
    int base = 2 * i;
    if (base >= n_pairs) return;

    const float NL2E = -1.4426950408889634f;
    float p00 = NL2E * pp[0], p01 = NL2E * pp[1];
    float p10 = (3.0f * NL2E) * pp[2], p11 = (3.0f * NL2E) * pp[3];
    float p20 = (3.0f * NL2E) * pp[4], p21 = (3.0f * NL2E) * pp[5];
    u64 P00 = pk2(p00, p00), P01 = pk2(p01, p01);
    u64 P10 = pk2(p10, p10), P11 = pk2(p11, p11);
    u64 P20 = pk2(p20, p20), P21 = pk2(p21, p21);

    float ax0, ay0, bx0, by0, ax1, ay1, bx1, by1;
    bool full = (base + 1 < n_pairs);
    if (full) {
        float4 a = x1[i];
        float4 b = x2[i];
        ax0 = a.x; ay0 = a.y; ax1 = a.z; ay1 = a.w;
        bx0 = b.x; by0 = b.y; bx1 = b.z; by1 = b.w;
    } else {
        const float2* x1s = reinterpret_cast<const float2*>(x1);
        const float2* x2s = reinterpret_cast<const float2*>(x2);
        float2 a = x1s[base];
        float2 b = x2s[base];
        ax0 = ax1 = a.x; ay0 = ay1 = a.y;
        bx0 = bx1 = b.x; by0 = by1 = b.y;
    }

    // ---- scalar per-pair prologue -------------------------------------
    float dx0 = bx0 - ax0, dy0 = by0 - ay0;
    float dx1 = bx1 - ax1, dy1 = by1 - ay1;
    float d2_0 = fmaf(dx0, dx0, dy0 * dy0);
    float d2_1 = fmaf(dx1, dx1, dy1 * dy1);
    float euc0 = __fsqrt_rn(d2_0);
    float euc1 = __fsqrt_rn(d2_1);

    // correctly-rounded euc/0.1 (== __fdiv_rn, fl(1/0.1f)==10.0f exactly)
    float t0 = euc0 * 10.0f;
    float nf0 = floorf(fmaf(fmaf(-0.1f, t0, euc0), 10.0f, t0)) + 1.0f;
    float t1 = euc1 * 10.0f;
    float nf1 = floorf(fmaf(fmaf(-0.1f, t1, euc1), 10.0f, t1)) + 1.0f;

    // warp-uniform max n (positive floats order as uint bit patterns)
    unsigned mk = __activemask();
    unsigned nmax_bits = __reduce_max_sync(mk, __float_as_uint(fmaxf(nf0, nf1)));
    float nmaxf = __uint_as_float(nmax_bits);

    float rs0 = rsq_ap(d2_0), rs1 = rsq_ap(d2_1);
    float h0 = (0.1f * dx0) * rs0, g0 = (0.1f * dy0) * rs0;
    float h1 = (0.1f * dx1) * rs1, g1 = (0.1f * dy1) * rs1;

    // ---- packed coefficient pipeline ----------------------------------
    u64 DX = pk2(dx0, dx1), DY = pk2(dy0, dy1);
    u64 X = pk2(ax0, ax1), Y = pk2(ay0, ay1);
    u64 H = pk2(h0, h1), G = pk2(g0, g1);

    u64 C0 = fma2(P01, DY, mul2(P00, DX));
    u64 C1 = fma2(P11, DY, mul2(P10, DX));
    u64 C2 = fma2(P21, DY, mul2(P20, DX));

    u64 XX = mul2(X, X), XY = mul2(X, Y), YY = mul2(Y, Y);
    u64 HH = mul2(H, H), HG = mul2(H, G), GG = mul2(G, G);
    u64 c2yy = mul2(C2, YY);
    u64 c2gg = mul2(C2, GG);

    u64 K0 = mul2(X, fma2(C0, XX, fma2(C1, XY, c2yy)));
    u64 K3 = mul2(H, fma2(C0, HH, fma2(C1, HG, c2gg)));

    u64 C0_3 = add2(C0, add2(C0, C0));
    u64 C1_2 = add2(C1, C1);
    u64 C2_2 = add2(C2, C2);

    u64 gx0 = fma2(C0_3, XX, fma2(C1_2, XY, c2yy));
    u64 gy0 = fma2(C1, XX, mul2(C2_2, XY));
    u64 K1 = fma2(G, gy0, mul2(H, gx0));
    u64 gx1 = fma2(C0_3, HH, fma2(C1_2, HG, c2gg));
    u64 gy1 = fma2(C1, HH, mul2(C2_2, HG));
    u64 K2 = fma2(Y, gy1, mul2(X, gx1));

    // ---- seeds: single chain only (4 packed ex2) -----------------------
    const u64 THREE2 = 0x4040000040400000ULL;  // {3,3}
    const u64 SIX2   = 0x40C0000040C00000ULL;  // {6,6}
    const u64 L2008  = 0xC0693574C0693574ULL;  // {log2(0.08), log2(0.08)}

    u64 DG  = add2(K1, add2(K2, K3));               // dg(0) = k1+k2+k3
    u64 tt  = fma2(K3, THREE2, K2);
    u64 D2G = add2(tt, tt);                         // d2g(0) = 2k2+6k3
    u64 W6  = mul2(K3, SIX2);                       // 6k3

    u64 E = ex2_2(add2(K0, L2008));   // 0.08 * 2^{g(0)}
    u64 R = ex2_2(DG);                // r(0)
    u64 Q = ex2_2(D2G);               // q(0)
    u64 W = ex2_2(W6);

    // ---- single chain: s=0 folded; s=1..11 always; 12..14 vote-gated ---
    u64 acc = E;                       // s=0 (n >= 1 always)
#pragma unroll
    for (int s = 1; s <= 11; ++s) {
        E = mul2(E, R);                // e(s)
        if (s < 11) R = mul2(R, Q);    // r(s)   (r10 is the last needed here)
        if (s < 10) Q = mul2(Q, W);    // q(s)   (q9 is the last needed here)
        float m0 = __saturatef(nf0 - (float)s);  // exactly 1.0 or 0.0
        float m1 = __saturatef(nf1 - (float)s);
        acc = fma2(E, pk2(m0, m1), acc);
    }
    if (nmaxf > 12.0f) {               // some pair in warp needs step 12
        Q = mul2(Q, W);                // q10
        R = mul2(R, Q);                // r11
        E = mul2(E, R);                // e(12)
        float m0 = __saturatef(nf0 - 12.0f);
        float m1 = __saturatef(nf1 - 12.0f);
        acc = fma2(E, pk2(m0, m1), acc);
        if (nmaxf > 13.0f) {           // step 13
            Q = mul2(Q, W);            // q11
            R = mul2(R, Q);            // r12
            E = mul2(E, R);            // e(13)
            m0 = __saturatef(nf0 - 13.0f);
            m1 = __saturatef(nf1 - 13.0f);
            acc = fma2(E, pk2(m0, m1), acc);
            if (nmaxf > 14.0f) {       // step 14 (n == 15)
                Q = mul2(Q, W);        // q12
                R = mul2(R, Q);        // r13
                E = mul2(E, R);        // e(14)
                m0 = __saturatef(nf0 - 14.0f);
                m1 = __saturatef(nf1 - 14.0f);
                acc = fma2(E, pk2(m0, m1), acc);
            }
        }
    }

    float a0, a1;
    upk2(a0, a1, acc);
    float c0 = fmaf(0.02f, nf0, a0);
    float c1 = fmaf(0.02f, nf1, a1);

    if (full) {
        *reinterpret_cast<float2*>(out + base) = make_float2(c0, c1);
    } else {
        out[base] = c0;
    }
}

extern "C" void kernel_launch(void* const* d_in, const int* in_sizes, int n_in,
                              void* d_out, int out_size) {
    const float4* x1 = (const float4*)d_in[0];
    const float4* x2 = (const float4*)d_in[1];
    const float*  pp = (const float*)d_in[2];
    float* out = (float*)d_out;

    int n_pairs = out_size;
    int n_threads_total = (n_pairs + 1) / 2;
    int threads = 256;
    int blocks = (n_threads_total + threads - 1) / threads;
    flow_cost_kernel<<<blocks, threads>>>(x1, x2, pp, out, n_pairs);
}